// round 4
// baseline (speedup 1.0000x reference)
#include <cuda_runtime.h>
#include <cuda_bf16.h>
#include <cstdint>

// ---------------- shapes (fixed by the problem) ----------------
#define B_   2048
#define F_   32
#define P_   64
#define E_   64
#define H_   128
#define M_   512      // K of GEMM2
#define D_   1024
#define EPSV 1e-5f

// ---------------- device scratch (no allocs allowed) ----------------
__device__ float g_C0[M_];
__device__ float g_C1[M_];
__device__ float g_v[M_];
__device__ float g_s1[M_], g_c1[M_];
__device__ float g_s2[D_], g_c2[D_];
__device__ float g_p[B_ * M_];
__device__ float g_q[B_ * M_];

// ---------------- f32x2 packed helpers (Blackwell) ----------------
__device__ __forceinline__ unsigned long long pk2(float x, float y) {
    unsigned long long r;
    asm("mov.b64 %0, {%1, %2};" : "=l"(r) : "f"(x), "f"(y));
    return r;
}
__device__ __forceinline__ void unpk2(unsigned long long v, float& x, float& y) {
    asm("mov.b64 {%0, %1}, %2;" : "=f"(x), "=f"(y) : "l"(v));
}
__device__ __forceinline__ unsigned long long ffma2(unsigned long long a,
                                                    unsigned long long b,
                                                    unsigned long long c) {
    unsigned long long d;
    asm("fma.rn.f32x2 %0, %1, %2, %3;" : "=l"(d) : "l"(a), "l"(b), "l"(c));
    return d;
}

// ---------------- prep0: fold constants ----------------
// C = We @ W1_top  (2 x 512), v = be @ W1_top, BN1/BN2 affine folds.
__global__ void prep0(const float* __restrict__ We, const float* __restrict__ be,
                      const float* __restrict__ W1,
                      const float* __restrict__ g1, const float* __restrict__ beta1,
                      const float* __restrict__ rm1, const float* __restrict__ rv1,
                      const float* __restrict__ b2, const float* __restrict__ g2,
                      const float* __restrict__ beta2,
                      const float* __restrict__ rm2, const float* __restrict__ rv2) {
    int m = threadIdx.x;  // 512 threads
    float c0 = 0.f, c1 = 0.f, vv = 0.f;
#pragma unroll 8
    for (int e = 0; e < E_; e++) {
        float w = W1[e * M_ + m];
        c0 += We[e] * w;          // We[0][e]
        c1 += We[E_ + e] * w;     // We[1][e]
        vv += be[e] * w;
    }
    g_C0[m] = c0;
    g_C1[m] = c1;
    g_v[m]  = vv;
    float s = g1[m] * rsqrtf(rv1[m] + EPSV);
    g_s1[m] = s;
    g_c1[m] = beta1[m] - s * rm1[m];
    for (int d = m; d < D_; d += M_) {
        float s2 = g2[d] * rsqrtf(rv2[d] + EPSV);
        g_s2[d] = s2;
        g_c2[d] = beta2[d] + s2 * (b2[d] - rm2[d]);
    }
}

// ---------------- prep1: build p,q (B x 512) ----------------
// t[b] = h[b] @ W1_bot; u[b] = pos[b] @ C; p = s1*(u+t+v+b1)+c1; q = s1*u
__global__ void prep1(const float* __restrict__ h, const float* __restrict__ pos,
                      const float* __restrict__ W1, const float* __restrict__ b1) {
    __shared__ float hs[8][H_];
    __shared__ float ps[8][2];
    int tid = threadIdx.x;       // 256
    int b0 = blockIdx.x * 8;     // grid 256
    for (int idx = tid; idx < 8 * H_; idx += 256) {
        int bb = idx >> 7, k = idx & 127;
        hs[bb][k] = h[(b0 + bb) * H_ + k];
    }
    if (tid < 16) ps[tid >> 1][tid & 1] = pos[b0 * 2 + tid];
    __syncthreads();

    int m0 = tid * 2;
    float acc[8][2];
#pragma unroll
    for (int bb = 0; bb < 8; bb++) { acc[bb][0] = 0.f; acc[bb][1] = 0.f; }
#pragma unroll 4
    for (int k = 0; k < H_; k++) {
        float2 w = *(const float2*)&W1[(E_ + k) * M_ + m0];
#pragma unroll
        for (int bb = 0; bb < 8; bb++) {
            float hv = hs[bb][k];
            acc[bb][0] += hv * w.x;
            acc[bb][1] += hv * w.y;
        }
    }
#pragma unroll
    for (int mm = 0; mm < 2; mm++) {
        int m = m0 + mm;
        float C0 = g_C0[m], C1 = g_C1[m], vv = g_v[m];
        float s = g_s1[m], cc = g_c1[m], bb1 = b1[m];
#pragma unroll
        for (int bb = 0; bb < 8; bb++) {
            float u = ps[bb][0] * C0 + ps[bb][1] * C1;
            float a = u + acc[bb][mm] + vv + bb1;
            g_p[(b0 + bb) * M_ + m] = s * a + cc;
            g_q[(b0 + bb) * M_ + m] = s * u;
        }
    }
}

// ---------------- main GEMM2 + max-pool ----------------
// per CTA: (f, i, d-tile of 256). A[j,k] = relu(p[f*64+j,k] - q[f*64+i,k]),
// C = A @ W2_tile (64 x 256), out[i,d] = relu(max_j (s2*C + c2)).
#define KC  16
#define DT  256
#define NCH (M_ / KC)   // 32 K-chunks

__global__ __launch_bounds__(256, 2) void mainK(const float* __restrict__ W2,
                                                float* __restrict__ out) {
    const int dt  = blockIdx.x;   // 0..3
    const int i   = blockIdx.y;   // 0..63
    const int f   = blockIdx.z;   // 0..31
    const int tid = threadIdx.x;
    const int tj  = tid >> 5;     // warp id 0..7 -> j-group of 8
    const int td  = tid & 31;     // lane -> d-group of 8
    const int dbase = dt * DT;

    __shared__ float qs[M_];
    __shared__ float zs[KC][P_];
    __shared__ float ws[KC][DT];
    __shared__ float red[8][DT];

    const float* qrow = g_q + (f * P_ + i) * M_;
    for (int m = tid; m < M_; m += 256) qs[m] = qrow[m];

    const float* prow = g_p + (size_t)(f * P_) * M_;

    // gmem staging thread maps
    const int pj  = tid >> 2;          // 0..63 (j row)
    const int pk4 = (tid & 3) * 4;     // 0,4,8,12 within K-chunk
    const int wk  = tid >> 6;          // 0..3
    const int wd  = (tid & 63) * 4;    // 0..252

    float4 pv;
    float4 wv[4];
    {
        pv = *(const float4*)&prow[pj * M_ + pk4];
#pragma unroll
        for (int r = 0; r < 4; r++)
            wv[r] = *(const float4*)&W2[(size_t)(wk + r * 4) * D_ + dbase + wd];
    }

    unsigned long long acc[8][4];
#pragma unroll
    for (int jj = 0; jj < 8; jj++)
#pragma unroll
        for (int pp = 0; pp < 4; pp++) acc[jj][pp] = 0ull;

    const int j0 = tj * 8;
    const int d0 = td * 8;

    __syncthreads();  // qs ready

    for (int c = 0; c < NCH; c++) {
        // stage current chunk into smem (z = relu(p - q))
        float4 q4 = *(const float4*)&qs[c * KC + pk4];
        zs[pk4 + 0][pj] = fmaxf(pv.x - q4.x, 0.f);
        zs[pk4 + 1][pj] = fmaxf(pv.y - q4.y, 0.f);
        zs[pk4 + 2][pj] = fmaxf(pv.z - q4.z, 0.f);
        zs[pk4 + 3][pj] = fmaxf(pv.w - q4.w, 0.f);
#pragma unroll
        for (int r = 0; r < 4; r++) *(float4*)&ws[wk + r * 4][wd] = wv[r];
        __syncthreads();

        // prefetch next chunk
        if (c + 1 < NCH) {
            int k0 = (c + 1) * KC;
            pv = *(const float4*)&prow[pj * M_ + k0 + pk4];
#pragma unroll
            for (int r = 0; r < 4; r++)
                wv[r] = *(const float4*)&W2[(size_t)(k0 + wk + r * 4) * D_ + dbase + wd];
        }

        // compute
#pragma unroll
        for (int k = 0; k < KC; k++) {
            float4 za = *(const float4*)&zs[k][j0];
            float4 zb = *(const float4*)&zs[k][j0 + 4];
            float4 wa = *(const float4*)&ws[k][d0];
            float4 wb = *(const float4*)&ws[k][d0 + 4];
            unsigned long long w01 = pk2(wa.x, wa.y);
            unsigned long long w23 = pk2(wa.z, wa.w);
            unsigned long long w45 = pk2(wb.x, wb.y);
            unsigned long long w67 = pk2(wb.z, wb.w);
            float zv[8] = {za.x, za.y, za.z, za.w, zb.x, zb.y, zb.z, zb.w};
#pragma unroll
            for (int jj = 0; jj < 8; jj++) {
                unsigned long long zz = pk2(zv[jj], zv[jj]);
                acc[jj][0] = ffma2(zz, w01, acc[jj][0]);
                acc[jj][1] = ffma2(zz, w23, acc[jj][1]);
                acc[jj][2] = ffma2(zz, w45, acc[jj][2]);
                acc[jj][3] = ffma2(zz, w67, acc[jj][3]);
            }
        }
        __syncthreads();
    }

    // epilogue: affine (folded BN2) then max over local 8 j's
    const int d0g = dbase + d0;
    float s2r[8], c2r[8], mx[8];
#pragma unroll
    for (int e = 0; e < 8; e++) {
        s2r[e] = g_s2[d0g + e];
        c2r[e] = g_c2[d0g + e];
        mx[e]  = -3.402823466e38f;
    }
#pragma unroll
    for (int jj = 0; jj < 8; jj++) {
#pragma unroll
        for (int pp = 0; pp < 4; pp++) {
            float x, y;
            unpk2(acc[jj][pp], x, y);
            int e0 = pp * 2;
            mx[e0]     = fmaxf(mx[e0],     s2r[e0]     * x + c2r[e0]);
            mx[e0 + 1] = fmaxf(mx[e0 + 1], s2r[e0 + 1] * y + c2r[e0 + 1]);
        }
    }
#pragma unroll
    for (int e = 0; e < 8; e++) red[tj][d0 + e] = mx[e];
    __syncthreads();
    if (tj == 0) {
#pragma unroll
        for (int e = 0; e < 8; e++) {
            float v = red[0][d0 + e];
#pragma unroll
            for (int w = 1; w < 8; w++) v = fmaxf(v, red[w][d0 + e]);
            out[(size_t)(f * P_ + i) * D_ + d0g + e] = fmaxf(v, 0.f);
        }
    }
}

// ---------------- launch ----------------
extern "C" void kernel_launch(void* const* d_in, const int* in_sizes, int n_in,
                              void* d_out, int out_size) {
    const float* h     = (const float*)d_in[0];   // (1,2048,128)
    const float* pos   = (const float*)d_in[1];   // (2048,2)
    // d_in[2] = seq_start_end (int64) — frames are equal-size, unused
    const float* We    = (const float*)d_in[3];   // (2,64)
    const float* be    = (const float*)d_in[4];   // (64)
    const float* W1    = (const float*)d_in[5];   // (192,512)
    const float* b1    = (const float*)d_in[6];   // (512)
    const float* g1    = (const float*)d_in[7];
    const float* beta1 = (const float*)d_in[8];
    const float* W2    = (const float*)d_in[9];   // (512,1024)
    const float* b2    = (const float*)d_in[10];
    const float* g2    = (const float*)d_in[11];
    const float* beta2 = (const float*)d_in[12];
    const float* rm1   = (const float*)d_in[13];
    const float* rv1   = (const float*)d_in[14];
    const float* rm2   = (const float*)d_in[15];
    const float* rv2   = (const float*)d_in[16];
    float* out = (float*)d_out;                   // (2048,1024)

    prep0<<<1, 512>>>(We, be, W1, g1, beta1, rm1, rv1, b2, g2, beta2, rm2, rv2);
    prep1<<<B_ / 8, 256>>>(h, pos, W1, b1);
    dim3 grid(D_ / DT, P_, F_);
    mainK<<<grid, 256>>>(W2, out);
}

// round 6
// speedup vs baseline: 4.3864x; 4.3864x over previous
#include <cuda_runtime.h>
#include <cuda_fp16.h>
#include <cstdint>

// ---------------- shapes ----------------
#define B_   2048
#define F_   32
#define P_   64
#define E_   64
#define H_   128
#define M_   512      // K of GEMM2
#define D_   1024
#define EPSV 1e-5f

// ---------------- device scratch ----------------
__device__ float g_C0[M_], g_C1[M_], g_v[M_], g_s1[M_], g_c1[M_];
__device__ float g_s2[D_], g_c2[D_];
__device__ float g_p[B_ * M_];
__device__ float g_q[B_ * M_];
// W2^T fp16: [dc(8)][d(128)][k(512) ^ ((d&7)<<3)]  (XOR-swizzled rows of 1KB)
__device__ __half g_Wh[8 * 128 * 512];

// ---------------- SMEM layout (bytes, dynamic) ----------------
#define SM_Q     0        // q_s[4][512] f32            = 8192
#define SM_P     8192     // p_s[64][68] f32 (padded)   = 17408
#define SM_W     25600    // W tile fp16 128x512 swizzl = 131072
#define SM_Z     156672   // z tile fp16 256x64 swizzl  = 32768
#define SM_TOTAL 189440

// ---------------- PTX helpers ----------------
__device__ __forceinline__ uint32_t smem_u32(const void* p) {
    uint32_t a;
    asm("{ .reg .u64 t; cvta.to.shared.u64 t, %1; cvt.u32.u64 %0, t; }" : "=r"(a) : "l"(p));
    return a;
}
__device__ __forceinline__ void ldsm4(uint32_t* r, uint32_t addr) {
    asm volatile("ldmatrix.sync.aligned.m8n8.x4.shared.b16 {%0,%1,%2,%3}, [%4];"
                 : "=r"(r[0]), "=r"(r[1]), "=r"(r[2]), "=r"(r[3]) : "r"(addr));
}
__device__ __forceinline__ void mma16816(float* c, const uint32_t* a,
                                         uint32_t b0, uint32_t b1) {
    asm volatile(
        "mma.sync.aligned.m16n8k16.row.col.f32.f16.f16.f32 "
        "{%0,%1,%2,%3}, {%4,%5,%6,%7}, {%8,%9}, {%0,%1,%2,%3};"
        : "+f"(c[0]), "+f"(c[1]), "+f"(c[2]), "+f"(c[3])
        : "r"(a[0]), "r"(a[1]), "r"(a[2]), "r"(a[3]), "r"(b0), "r"(b1));
}

// ---------------- prep0: fold constants ----------------
__global__ void prep0(const float* __restrict__ We, const float* __restrict__ be,
                      const float* __restrict__ W1,
                      const float* __restrict__ g1, const float* __restrict__ beta1,
                      const float* __restrict__ rm1, const float* __restrict__ rv1,
                      const float* __restrict__ b2, const float* __restrict__ g2,
                      const float* __restrict__ beta2,
                      const float* __restrict__ rm2, const float* __restrict__ rv2) {
    int m = threadIdx.x;  // 512
    float c0 = 0.f, c1 = 0.f, vv = 0.f;
#pragma unroll 8
    for (int e = 0; e < E_; e++) {
        float w = W1[e * M_ + m];
        c0 += We[e] * w;
        c1 += We[E_ + e] * w;
        vv += be[e] * w;
    }
    g_C0[m] = c0;
    g_C1[m] = c1;
    g_v[m]  = vv;
    float s = g1[m] * rsqrtf(rv1[m] + EPSV);
    g_s1[m] = s;
    g_c1[m] = beta1[m] - s * rm1[m];
    for (int d = m; d < D_; d += M_) {
        float s2 = g2[d] * rsqrtf(rv2[d] + EPSV);
        g_s2[d] = s2;
        g_c2[d] = beta2[d] + s2 * (b2[d] - rm2[d]);
    }
}

// ---------------- prep1: build p,q ----------------
__global__ void prep1(const float* __restrict__ h, const float* __restrict__ pos,
                      const float* __restrict__ W1, const float* __restrict__ b1) {
    __shared__ float hs[8][H_];
    __shared__ float ps[8][2];
    int tid = threadIdx.x;
    int b0 = blockIdx.x * 8;
    for (int idx = tid; idx < 8 * H_; idx += 256) {
        int bb = idx >> 7, k = idx & 127;
        hs[bb][k] = h[(b0 + bb) * H_ + k];
    }
    if (tid < 16) ps[tid >> 1][tid & 1] = pos[b0 * 2 + tid];
    __syncthreads();

    int m0 = tid * 2;
    float acc[8][2];
#pragma unroll
    for (int bb = 0; bb < 8; bb++) { acc[bb][0] = 0.f; acc[bb][1] = 0.f; }
#pragma unroll 4
    for (int k = 0; k < H_; k++) {
        float2 w = *(const float2*)&W1[(E_ + k) * M_ + m0];
#pragma unroll
        for (int bb = 0; bb < 8; bb++) {
            float hv = hs[bb][k];
            acc[bb][0] += hv * w.x;
            acc[bb][1] += hv * w.y;
        }
    }
#pragma unroll
    for (int mm = 0; mm < 2; mm++) {
        int m = m0 + mm;
        float C0 = g_C0[m], C1 = g_C1[m], vv = g_v[m];
        float s = g_s1[m], cc = g_c1[m], bb1 = b1[m];
#pragma unroll
        for (int bb = 0; bb < 8; bb++) {
            float u = ps[bb][0] * C0 + ps[bb][1] * C1;
            float a = u + acc[bb][mm] + vv + bb1;
            g_p[(b0 + bb) * M_ + m] = s * a + cc;
            g_q[(b0 + bb) * M_ + m] = s * u;
        }
    }
}

// ---------------- prep2: W2^T -> fp16 swizzled ----------------
__global__ void prep2(const float* __restrict__ W2) {
    int dc = blockIdx.x;   // 0..7
    int ks = blockIdx.y;   // 0..7 (k-slab of 64)
    for (int idx = threadIdx.x; idx < 8192; idx += 256) {
        int d = idx & 127;                 // coalesced over d
        int k = ks * 64 + (idx >> 7);
        float w = W2[(size_t)k * D_ + dc * 128 + d];
        int kk = k ^ ((d & 7) << 3);
        g_Wh[dc * 65536 + d * 512 + kk] = __float2half_rn(w);
    }
}

// ---------------- main: mma.sync GEMM2 + max-pool ----------------
__global__ __launch_bounds__(256, 1) void mainK(float* __restrict__ out) {
    extern __shared__ char smem[];
    float* q_s = (float*)(smem + SM_Q);
    float* p_s = (float*)(smem + SM_P);

    const int tid  = threadIdx.x;
    const int lane = tid & 31;
    const int wid  = tid >> 5;
    const int wn   = wid >> 1;   // i_local 0..3
    const int wd   = wid & 1;    // d-half 0..1
    const int dc   = blockIdx.x; // 0..7
    const int f    = blockIdx.y; // 0..31

    const uint32_t w_u = smem_u32(smem + SM_W);
    const uint32_t z_u = smem_u32(smem + SM_Z);

    // ---- stage W tile (pre-swizzled 128KB) ----
    {
        const uint4* src = (const uint4*)(g_Wh + (size_t)dc * 65536);
        uint4* dst = (uint4*)(smem + SM_W);
#pragma unroll
        for (int r = 0; r < 32; r++) dst[tid + r * 256] = src[tid + r * 256];
    }

    // ---- ldmatrix address precompute ----
    // A (W): matrices m0:d[0..7]xk_lo m1:d[8..15]xk_lo m2:d[0..7]xk_hi m3:d[8..15]xk_hi
    uint32_t arow[4];
#pragma unroll
    for (int mt = 0; mt < 4; mt++) {
        int d = wd * 64 + mt * 16 + (lane & 15);
        arow[mt] = w_u + d * 1024;
    }
    const uint32_t axor  = (uint32_t)((lane & 7) << 4);
    const uint32_t akoff = (uint32_t)((lane >> 4) << 4);   // +16B for k_hi lanes
    // B (z): n = wn*64 + ntp*16 + (lane&7) + ((lane&16)?8:0), k_hi for lanes 8-15/24-31
    const int nbase = wn * 64 + (lane & 7) + ((lane & 16) ? 8 : 0);
    const uint32_t brow0 = z_u + nbase * 128;
    const uint32_t bxor  = axor;                            // (n&7)<<4 == (lane&7)<<4
    const uint32_t bkoff = (uint32_t)((lane & 8) << 1);     // +16B for k_hi lanes

    // ---- BN2 affine constants for this thread's 8 d-rows ----
    float s2r[8], c2r[8];
#pragma unroll
    for (int mt = 0; mt < 4; mt++)
#pragma unroll
        for (int dr = 0; dr < 2; dr++) {
            int dgl = dc * 128 + wd * 64 + mt * 16 + (lane >> 2) + 8 * dr;
            s2r[mt * 2 + dr] = g_s2[dgl];
            c2r[mt * 2 + dr] = g_c2[dgl];
        }

    const int pj = tid >> 2;          // p-stage row
    const int pc = tid & 3;           // p-stage 16-float col group
    const int bj = tid & 63;          // build: j
    const int bi = tid >> 6;          // build: i_local

    for (int ig = 0; ig < 16; ig++) {
        // ---- stage q[4][512] for this i-group ----
#pragma unroll
        for (int r = 0; r < 2; r++) {
            int idx = tid + r * 256;
            int il = idx >> 7, kq = idx & 127;
            float4 v = *(const float4*)&g_q[(size_t)(f * 64 + ig * 4 + il) * 512 + kq * 4];
            *(float4*)&q_s[il * 512 + kq * 4] = v;
        }

        float acc[4][8][4];
#pragma unroll
        for (int mt = 0; mt < 4; mt++)
#pragma unroll
            for (int nt = 0; nt < 8; nt++)
#pragma unroll
                for (int e = 0; e < 4; e++) acc[mt][nt][e] = 0.f;

        for (int kc = 0; kc < 8; kc++) {
            // LDG p chunk (latency overlapped with the barrier)
            float4 pr[4];
            {
                const float* src = g_p + (size_t)(f * 64 + pj) * 512 + kc * 64 + pc * 16;
#pragma unroll
                for (int r = 0; r < 4; r++) pr[r] = *(const float4*)(src + r * 4);
            }
            __syncthreads();   // prev mma done with z buffer; q/W staged (first iter)
#pragma unroll
            for (int r = 0; r < 4; r++)
                *(float4*)&p_s[pj * 68 + pc * 16 + r * 4] = pr[r];
            __syncthreads();   // p_s ready

            // ---- build z = relu(p - q) fp16, swizzled [n=tid][64k] ----
            {
                const float4* pp = (const float4*)(p_s + bj * 68);
                const float4* qq = (const float4*)(q_s + bi * 512 + kc * 64);
                char* zb = smem + SM_Z + tid * 128;
                const uint32_t zx = (uint32_t)((tid & 7) << 4);
#pragma unroll
                for (int v = 0; v < 8; v++) {
                    float4 a0 = pp[v * 2],     a1 = pp[v * 2 + 1];
                    float4 b0 = qq[v * 2],     b1 = qq[v * 2 + 1];
                    __half2 h0 = __floats2half2_rn(fmaxf(a0.x - b0.x, 0.f), fmaxf(a0.y - b0.y, 0.f));
                    __half2 h1 = __floats2half2_rn(fmaxf(a0.z - b0.z, 0.f), fmaxf(a0.w - b0.w, 0.f));
                    __half2 h2 = __floats2half2_rn(fmaxf(a1.x - b1.x, 0.f), fmaxf(a1.y - b1.y, 0.f));
                    __half2 h3 = __floats2half2_rn(fmaxf(a1.z - b1.z, 0.f), fmaxf(a1.w - b1.w, 0.f));
                    uint4 pk;
                    pk.x = *reinterpret_cast<uint32_t*>(&h0);
                    pk.y = *reinterpret_cast<uint32_t*>(&h1);
                    pk.z = *reinterpret_cast<uint32_t*>(&h2);
                    pk.w = *reinterpret_cast<uint32_t*>(&h3);
                    *(uint4*)(zb + (((uint32_t)(v * 16)) ^ zx)) = pk;
                }
            }
            __syncthreads();   // z ready

            // ---- mma over 4 k16 steps ----
#pragma unroll
            for (int k16 = 0; k16 < 4; k16++) {
                const uint32_t kbyteA = (uint32_t)(kc * 128 + k16 * 32);
                uint32_t a[4][4];
#pragma unroll
                for (int mt = 0; mt < 4; mt++)
                    ldsm4(a[mt], arow[mt] + ((kbyteA + akoff) ^ axor));
                const uint32_t kbyteB = (uint32_t)(k16 * 32);
#pragma unroll
                for (int ntp = 0; ntp < 4; ntp++) {
                    uint32_t b[4];
                    ldsm4(b, brow0 + ntp * 2048 + ((kbyteB + bkoff) ^ bxor));
#pragma unroll
                    for (int mt = 0; mt < 4; mt++) {
                        mma16816(acc[mt][2 * ntp],     a[mt], b[0], b[1]);
                        mma16816(acc[mt][2 * ntp + 1], a[mt], b[2], b[3]);
                    }
                }
            }
        }

        // ---- epilogue: affine -> max over 64 j -> relu -> store ----
#pragma unroll
        for (int mt = 0; mt < 4; mt++)
#pragma unroll
            for (int dr = 0; dr < 2; dr++) {
                float s = s2r[mt * 2 + dr], cb = c2r[mt * 2 + dr];
                float m = -3.402823466e38f;
#pragma unroll
                for (int nt = 0; nt < 8; nt++) {
                    m = fmaxf(m, fmaf(s, acc[mt][nt][dr * 2 + 0], cb));
                    m = fmaxf(m, fmaf(s, acc[mt][nt][dr * 2 + 1], cb));
                }
                m = fmaxf(m, __shfl_xor_sync(0xffffffffu, m, 1));
                m = fmaxf(m, __shfl_xor_sync(0xffffffffu, m, 2));
                if ((lane & 3) == 0) {
                    int dgl = dc * 128 + wd * 64 + mt * 16 + (lane >> 2) + 8 * dr;
                    out[(size_t)(f * 64 + ig * 4 + wn) * D_ + dgl] = fmaxf(m, 0.f);
                }
            }
    }
}

// ---------------- launch ----------------
extern "C" void kernel_launch(void* const* d_in, const int* in_sizes, int n_in,
                              void* d_out, int out_size) {
    const float* h     = (const float*)d_in[0];
    const float* pos   = (const float*)d_in[1];
    const float* We    = (const float*)d_in[3];
    const float* be    = (const float*)d_in[4];
    const float* W1    = (const float*)d_in[5];
    const float* b1    = (const float*)d_in[6];
    const float* g1    = (const float*)d_in[7];
    const float* beta1 = (const float*)d_in[8];
    const float* W2    = (const float*)d_in[9];
    const float* b2    = (const float*)d_in[10];
    const float* g2    = (const float*)d_in[11];
    const float* beta2 = (const float*)d_in[12];
    const float* rm1   = (const float*)d_in[13];
    const float* rv1   = (const float*)d_in[14];
    const float* rm2   = (const float*)d_in[15];
    const float* rv2   = (const float*)d_in[16];
    float* out = (float*)d_out;

    prep0<<<1, 512>>>(We, be, W1, g1, beta1, rm1, rv1, b2, g2, beta2, rm2, rv2);
    prep1<<<B_ / 8, 256>>>(h, pos, W1, b1);
    prep2<<<dim3(8, 8), 256>>>(W2);
    cudaFuncSetAttribute(mainK, cudaFuncAttributeMaxDynamicSharedMemorySize, SM_TOTAL);
    mainK<<<dim3(8, F_), 256, SM_TOTAL>>>(out);
}